// round 16
// baseline (speedup 1.0000x reference)
#include <cuda_runtime.h>
#include <cuda_bf16.h>
#include <math.h>
#include <stdint.h>

// ---------------------------------------------------------------------------
// GPTrack2D encoder — tf32 mma.sync, pre-converted operands, BK=32 3-stage
// pipeline, merged fwd/bwd dirs. R15 additions:
//  * G-factorization: attn = q @ G with G^{(dir,b)} = vstack_h(kv_h@Wout_h);
//    o_kernel removed, q emitted as tf32 by the qkv epilogue.
//  * EPI4 accumulates both dirs into one pos-/zero-preinitialized buffer;
//    combine passes removed.
// ---------------------------------------------------------------------------

#define Bc 2
#define Lc 12
#define Nc 1024
#define Dc 768
#define Hc 12
#define Mc 3072
#define D3c 2304
#define BNc (Bc*Nc)          /* 2048 */
#define BLNc (Bc*Lc*Nc)      /* 24576 */
#define NDc (Nc*Dc)
#define LNDc (Lc*Nc*Dc)
#define TOTc (Bc*Lc*Nc*Dc)
#define BNDc (Bc*Nc*Dc)

// ------------------------- device scratch (no allocs) ----------------------
__device__ float    g_pos   [TOTc];
__device__ float    g_xa    [TOTc];
__device__ float    g_xb    [TOTc];
__device__ float    g_h     [2*BNDc];
__device__ float    g_qkvpre[2l*BLNc*D3c];
__device__ float    g_qkv   [2*BNc*D3c];
__device__ float    g_kvp   [2*Bc*Hc*8*64*64];
__device__ float    g_x2    [2*BNDc];
// tf32-bit-pattern (u32) activations
__device__ unsigned g_xnall [2*BLNc*Dc];
__device__ unsigned g_hn    [2*BNDc];
__device__ unsigned g_ln2   [2*BNDc];
__device__ unsigned g_q     [2*BNc*Dc];
__device__ unsigned g_t1    [2*BNc*Mc];
__device__ unsigned g_G     [4*Dc*Dc];      // [dir*2+b][768][768]
// tf32 weights ([s4][K][N], converted)
__device__ unsigned g_Wqkv  [4*Dc*D3c];
__device__ unsigned g_Wqkvh [4*Dc*D3c];
__device__ unsigned g_W1    [4*Dc*Mc];
__device__ unsigned g_W2    [4*Mc*Dc];

__device__ __forceinline__ float gelu_f(float x) {
    return 0.5f * x * (1.0f + erff(x * 0.70710678118654752440f));
}
__device__ __forceinline__ unsigned f2tf32(float x) {
    unsigned r;
    asm("cvt.rna.tf32.f32 %0, %1;" : "=r"(r) : "f"(x));
    return r;
}
__device__ __forceinline__ void mma_tf32(float c[4], unsigned a0, unsigned a1,
                                         unsigned a2, unsigned a3,
                                         unsigned b0, unsigned b1) {
    asm volatile(
        "mma.sync.aligned.m16n8k8.row.col.f32.tf32.tf32.f32 "
        "{%0,%1,%2,%3},{%4,%5,%6,%7},{%8,%9},{%0,%1,%2,%3};"
        : "+f"(c[0]), "+f"(c[1]), "+f"(c[2]), "+f"(c[3])
        : "r"(a0), "r"(a1), "r"(a2), "r"(a3), "r"(b0), "r"(b1));
}
__device__ __forceinline__ void cp16(unsigned* sdst, const void* gsrc) {
    unsigned s = (unsigned)__cvta_generic_to_shared(sdst);
    asm volatile("cp.async.cg.shared.global [%0], [%1], 16;" :: "r"(s), "l"(gsrc));
}

// ------------------------------- elementwise -------------------------------
__global__ void pos_kernel(const float* __restrict__ tpos,
                           const float* __restrict__ spos,
                           float* __restrict__ pos) {
    int idx = blockIdx.x * blockDim.x + threadIdx.x;
    if (idx >= TOTc) return;
    int d = idx % Dc;
    int n = (idx / Dc) % Nc;
    int l = (idx / NDc) % Lc;
    int b = idx / LNDc;
    pos[idx] = tpos[(b * Lc + l) * Dc + d] * spos[(b * Nc + n) * Dc + d];
}
__global__ void vadd_kernel(const float* __restrict__ a,
                            const float* __restrict__ b,
                            float* __restrict__ c, int n) {
    int idx = blockIdx.x * blockDim.x + threadIdx.x;
    if (idx < n) c[idx] = a[idx] + b[idx];
}
__global__ void copy_kernel(const float* __restrict__ a,
                            float* __restrict__ b, int n) {
    int idx = blockIdx.x * blockDim.x + threadIdx.x;
    if (idx < n) b[idx] = a[idx];
}
__global__ void zero_kernel(float* __restrict__ p, int n) {
    int idx = blockIdx.x * blockDim.x + threadIdx.x;
    if (idx < n) p[idx] = 0.0f;
}
__global__ void hinit_kernel(const float* __restrict__ src,
                             float* __restrict__ h) {
    int idx = blockIdx.x * blockDim.x + threadIdx.x;
    if (idx < BNDc) { h[idx] = src[idx]; h[idx + BNDc] = src[idx]; }
}
__global__ void wconv_kernel(const float* __restrict__ in,
                             unsigned* __restrict__ out, long n) {
    long idx = (long)blockIdx.x * blockDim.x + threadIdx.x;
    if (idx < n) out[idx] = f2tf32(in[idx]);
}

// ------------------------------- layernorm ---------------------------------
__device__ __forceinline__ void ln_row(float v0, float v1, float v2,
                                       const float* __restrict__ gam,
                                       const float* __restrict__ bet,
                                       unsigned* __restrict__ dp, int t,
                                       float* red) {
    float s = v0 + v1 + v2;
    #pragma unroll
    for (int o = 16; o > 0; o >>= 1) s += __shfl_down_sync(0xffffffffu, s, o);
    if ((t & 31) == 0) red[t >> 5] = s;
    __syncthreads();
    if (t < 32) {
        float x = (t < 8) ? red[t] : 0.0f;
        #pragma unroll
        for (int o = 4; o > 0; o >>= 1) x += __shfl_down_sync(0xffffffffu, x, o);
        if (t == 0) red[0] = x;
    }
    __syncthreads();
    float m = red[0] * (1.0f / 768.0f);
    __syncthreads();
    float d0 = v0 - m, d1 = v1 - m, d2 = v2 - m;
    float q2 = d0 * d0 + d1 * d1 + d2 * d2;
    #pragma unroll
    for (int o = 16; o > 0; o >>= 1) q2 += __shfl_down_sync(0xffffffffu, q2, o);
    if ((t & 31) == 0) red[t >> 5] = q2;
    __syncthreads();
    if (t < 32) {
        float x = (t < 8) ? red[t] : 0.0f;
        #pragma unroll
        for (int o = 4; o > 0; o >>= 1) x += __shfl_down_sync(0xffffffffu, x, o);
        if (t == 0) red[0] = x;
    }
    __syncthreads();
    float r = rsqrtf(red[0] * (1.0f / 768.0f) + 1e-5f);
    dp[t]       = f2tf32(d0 * r * gam[t]       + bet[t]);
    dp[t + 256] = f2tf32(d1 * r * gam[t + 256] + bet[t + 256]);
    dp[t + 512] = f2tf32(d2 * r * gam[t + 512] + bet[t + 512]);
}

__global__ void ln_xall_m(const float* __restrict__ X,
                          const float* __restrict__ gbase,
                          const float* __restrict__ bbase,
                          unsigned* __restrict__ dst) {
    __shared__ float red[32];
    int R = blockIdx.x;
    int z = R / BLNc;
    int R2 = R - z * BLNc;
    int tt = R2 / BNc;
    int rr = R2 - tt * BNc;
    int b = rr >> 10, n = rr & 1023;
    const float* p = X + (long)b * LNDc + (long)tt * NDc + (long)n * Dc;
    const float* gam = gbase + (long)z * 2 * Dc;
    const float* bet = bbase + (long)z * 2 * Dc;
    int t = threadIdx.x;
    ln_row(p[t], p[t + 256], p[t + 512], gam, bet, dst + (long)R * Dc, t, red);
}

__global__ void ln_h_m(const float* __restrict__ h,
                       const float* __restrict__ pos, int tp0, int tp1,
                       const float* __restrict__ gbase,
                       const float* __restrict__ bbase,
                       unsigned* __restrict__ dst) {
    __shared__ float red[32];
    int row = blockIdx.x;
    int z = row >> 11;
    int lrow = row & 2047;
    int b = lrow >> 10, n = lrow & 1023;
    const float* p = h + (long)row * Dc;
    int tp = z ? tp1 : tp0;
    const float* q = pos + (long)b * LNDc + (long)tp * NDc + (long)n * Dc;
    const float* gam = gbase + (long)z * 2 * Dc;
    const float* bet = bbase + (long)z * 2 * Dc;
    int t = threadIdx.x;
    ln_row(p[t] + q[t], p[t + 256] + q[t + 256], p[t + 512] + q[t + 512],
           gam, bet, dst + (long)row * Dc, t, red);
}

__global__ void ln2_m(const float* __restrict__ x2,
                      const float* __restrict__ gbase,
                      const float* __restrict__ bbase,
                      unsigned* __restrict__ dst) {
    __shared__ float red[32];
    int row = blockIdx.x;
    int z = row >> 11;
    const float* p = x2 + (long)row * Dc;
    const float* gam = gbase + (long)z * 2 * Dc;
    const float* bet = bbase + (long)z * 2 * Dc;
    int t = threadIdx.x;
    ln_row(p[t], p[t + 256], p[t + 512], gam, bet, dst + (long)row * Dc, t, red);
}

// ----------------------------- tf32 MMA GEMM -------------------------------
// C[Mtot,N] = A[Mtot,K] @ B_sel[K,N] + bias_dir.
// B select: dirB = row0 / bselr (2 dirs for weights; 4 (dir,b) slots for G).
// bias/t select: dir = row0 / Mper. BM=128, BN=128, BK=32, 128 thr, 3-stage.
struct EpiAux {
    const float* pre; int t0, t1;  // EPI2 (+ EPI3/4 reuse t0/t1)
    unsigned* qo;                  // EPI2: q out (tf32 bits)
    const float* X;                // EPI3
    float* h;                      // EPI3 [2*BNDc]
    const float* pos; int tp0, tp1;// EPI3
    float* x2w;                    // EPI3 [2*BNDc]
    const float* x2r;              // EPI4
    float* y;                      // EPI4: accumulate (+=), both dirs
    unsigned* t1o;                 // EPI1
};

#define ASTR 36
#define BSTR 136
#define A_ST (128 * ASTR)
#define B_ST (32 * BSTR)
#define TG_SMEM (3 * (A_ST + B_ST) * 4)   /* 107,520 B */

template<int EPI>
__global__ void __launch_bounds__(128)
tgemm(const unsigned* __restrict__ A, int lda,
      const unsigned* __restrict__ B, long bzstr, int ldb,
      const float* __restrict__ bias, long bizstr,
      float* __restrict__ C, int N, int K, int Mper, int bselr, EpiAux aux) {
    extern __shared__ unsigned smem[];
    unsigned* Asm = smem;                    // [3][128][ASTR]
    unsigned* Bsm = smem + 3 * A_ST;         // [3][32][BSTR]

    const int tid = threadIdx.x;
    const int lane = tid & 31;
    const int wid = tid >> 5;
    const int warp_m = (wid >> 1) * 64;
    const int warp_n = (wid & 1) * 64;
    const int bx = blockIdx.x, by = blockIdx.y;
    const int r = lane >> 2, cq = lane & 3;
    const int row0 = by * 128;
    const int dir = (row0 >= Mper) ? 1 : 0;
    const int dirB = row0 / bselr;
    const unsigned* Bd = B + (long)dirB * bzstr;
    const float* biasd = bias + (long)dir * bizstr;

    float acc[4][8][4];
    #pragma unroll
    for (int i = 0; i < 4; i++)
        #pragma unroll
        for (int j = 0; j < 8; j++)
            #pragma unroll
            for (int q = 0; q < 4; q++) acc[i][j][q] = 0.0f;

    const int S = K / 32;

    auto issue_stage = [&](int s) {
        int st = s % 3;
        int k0 = s * 32;
        unsigned* Ad = Asm + st * A_ST;
        unsigned* Bs = Bsm + st * B_ST;
        #pragma unroll
        for (int i = 0; i < 8; i++) {
            int lid = tid + i * 128;
            int am = lid >> 3, ak = (lid & 7) * 4;
            cp16(Ad + am * ASTR + ak, A + (long)(row0 + am) * lda + k0 + ak);
        }
        #pragma unroll
        for (int i = 0; i < 8; i++) {
            int lid = tid + i * 128;
            int br = lid >> 5, bc = (lid & 31) * 4;
            cp16(Bs + br * BSTR + bc, Bd + (long)(k0 + br) * ldb + bx * 128 + bc);
        }
    };

    issue_stage(0);
    asm volatile("cp.async.commit_group;");
    issue_stage(1);
    asm volatile("cp.async.commit_group;");

    for (int s = 0; s < S; s++) {
        if (s + 2 < S) {
            issue_stage(s + 2);
            asm volatile("cp.async.commit_group;");
            asm volatile("cp.async.wait_group 2;");
        } else if (s + 1 < S) {
            asm volatile("cp.async.wait_group 1;");
        } else {
            asm volatile("cp.async.wait_group 0;");
        }
        __syncthreads();
        const int st = s % 3;
        const unsigned* Ad = Asm + st * A_ST;
        const unsigned* Bs = Bsm + st * B_ST;
        #pragma unroll
        for (int ka = 0; ka < 4; ka++) {
            const int kb = ka * 8;
            unsigned af[4][4], bf[8][2];
            #pragma unroll
            for (int mi = 0; mi < 4; mi++) {
                int m0 = warp_m + mi * 16 + r;
                af[mi][0] = Ad[m0 * ASTR + kb + cq];
                af[mi][1] = Ad[(m0 + 8) * ASTR + kb + cq];
                af[mi][2] = Ad[m0 * ASTR + kb + cq + 4];
                af[mi][3] = Ad[(m0 + 8) * ASTR + kb + cq + 4];
            }
            #pragma unroll
            for (int ni = 0; ni < 8; ni++) {
                int n0 = warp_n + ni * 8 + r;
                bf[ni][0] = Bs[(kb + cq) * BSTR + n0];
                bf[ni][1] = Bs[(kb + cq + 4) * BSTR + n0];
            }
            #pragma unroll
            for (int mi = 0; mi < 4; mi++)
                #pragma unroll
                for (int ni = 0; ni < 8; ni++)
                    mma_tf32(acc[mi][ni], af[mi][0], af[mi][1], af[mi][2],
                             af[mi][3], bf[ni][0], bf[ni][1]);
        }
        __syncthreads();
    }

    // ---- epilogue ----
    const int t_z  = dir ? aux.t1 : aux.t0;
    const int tp_z = dir ? aux.tp1 : aux.tp0;
    #pragma unroll
    for (int mi = 0; mi < 4; mi++) {
        #pragma unroll
        for (int ni = 0; ni < 8; ni++) {
            int col = bx * 128 + warp_n + ni * 8 + 2 * cq;
            float bs0 = biasd[col], bs1 = biasd[col + 1];
            #pragma unroll
            for (int half = 0; half < 2; half++) {
                int row = row0 + warp_m + mi * 16 + r + half * 8;
                float v0 = acc[mi][ni][half * 2 + 0] + bs0;
                float v1 = acc[mi][ni][half * 2 + 1] + bs1;
                if (EPI == 0) {
                    float* cp = C + (long)row * N + col;
                    cp[0] = v0; cp[1] = v1;
                } else if (EPI == 1) {
                    unsigned* tp = aux.t1o + (long)row * N + col;
                    tp[0] = f2tf32(gelu_f(v0));
                    tp[1] = f2tf32(gelu_f(v1));
                } else if (EPI == 2) {
                    int lrow = row - dir * 2048;
                    const float* pp = aux.pre
                        + ((long)dir * Lc + t_z) * BNc * D3c
                        + (long)lrow * D3c + col;
                    v0 += pp[0]; v1 += pp[1];
                    if (col < 1536) {
                        v0 = (v0 > 0.f) ? v0 + 1.f : expf(v0);
                        v1 = (v1 > 0.f) ? v1 + 1.f : expf(v1);
                    }
                    if (col < 768) {        // q -> tf32 buffer
                        unsigned* qp = aux.qo + (long)row * Dc + col;
                        qp[0] = f2tf32(v0); qp[1] = f2tf32(v1);
                    } else {                // k, v -> f32 qkv buffer
                        float* cp = C + (long)row * N + col;
                        cp[0] = v0; cp[1] = v1;
                    }
                } else if (EPI == 3) {
                    int lrow = row & 2047;
                    int b = lrow >> 10, rr = lrow & 1023;
                    long xb = (long)b * LNDc + (long)t_z * NDc + (long)rr * Dc + col;
                    long pb = (long)b * LNDc + (long)tp_z * NDc + (long)rr * Dc + col;
                    long idx = (long)row * Dc + col;
                    aux.x2w[idx]     = v0 + aux.X[xb];
                    aux.x2w[idx + 1] = v1 + aux.X[xb + 1];
                    aux.h[idx]     = v0 + aux.h[idx]     + aux.pos[pb];
                    aux.h[idx + 1] = v1 + aux.h[idx + 1] + aux.pos[pb + 1];
                } else if (EPI == 4) {
                    int lrow = row & 2047;
                    int b = lrow >> 10, rr = lrow & 1023;
                    long idx = (long)row * Dc + col;
                    long yo = (long)b * LNDc + (long)t_z * NDc + (long)rr * Dc + col;
                    aux.y[yo]     += v0 + aux.x2r[idx];
                    aux.y[yo + 1] += v1 + aux.x2r[idx + 1];
                }
            }
        }
    }
}

// ----------------------- linear-attention kv + G ---------------------------
__global__ void kv_partial_m(const float* __restrict__ qkvg,
                             float* __restrict__ kvpg) {
    int z = blockIdx.y;
    const float* qkv = qkvg + (long)z * BNc * D3c;
    float* kvp = kvpg + (long)z * Bc * Hc * 8 * 4096;
    int chunk = blockIdx.x & 7;
    int bh = blockIdx.x >> 3;
    int h = bh % Hc, b = bh / Hc;
    int t = threadIdx.x;
    __shared__ float ks[8][64], vs[8][64];
    int d0 = (t & 15) * 4, e0 = (t >> 4) * 4;
    float acc[4][4];
    #pragma unroll
    for (int i = 0; i < 4; i++)
        #pragma unroll
        for (int j = 0; j < 4; j++) acc[i][j] = 0.0f;
    int j0 = chunk * 128;
    const float* kbase = qkv + (long)(b * Nc) * D3c + Dc + h * 64;
    const float* vbase = kbase + Dc;
    for (int js = 0; js < 128; js += 8) {
        #pragma unroll
        for (int rr = 0; rr < 2; rr++) {
            int id = t + rr * 256;
            int jj = id >> 6, dd = id & 63;
            long roff = (long)(j0 + js + jj) * D3c + dd;
            ks[jj][dd] = kbase[roff];
            vs[jj][dd] = vbase[roff];
        }
        __syncthreads();
        #pragma unroll
        for (int jj = 0; jj < 8; jj++) {
            float kd[4], ve[4];
            *(float4*)kd = *(const float4*)&ks[jj][d0];
            *(float4*)ve = *(const float4*)&vs[jj][e0];
            #pragma unroll
            for (int i = 0; i < 4; i++)
                #pragma unroll
                for (int j = 0; j < 4; j++)
                    acc[i][j] = fmaf(kd[i], ve[j], acc[i][j]);
        }
        __syncthreads();
    }
    float* dst = kvp + ((long)bh * 8 + chunk) * 4096;
    #pragma unroll
    for (int i = 0; i < 4; i++)
        #pragma unroll
        for (int j = 0; j < 4; j++)
            dst[(d0 + i) * 64 + e0 + j] = acc[i][j];
}

// G^{(zb)}[h*64+d, col] = sum_e kv^{(z,b,h)}[d,e] * Wout^{(z*2+layer)}[h*64+e, col]
__global__ void kvG_kernel(const float* __restrict__ kvpg,
                           const float* __restrict__ WoutAll, int layer,
                           unsigned* __restrict__ G) {
    int h = blockIdx.x;          // 0..11
    int zb = blockIdx.y;         // 0..3 : z*2+b
    int z = zb >> 1, b = zb & 1;
    const float* kvp = kvpg + ((long)z * Bc * Hc + (long)b * Hc + h) * 8 * 4096;
    __shared__ float kv[64][65];
    int t = threadIdx.x;         // 256
    for (int x = t; x < 4096; x += 256) {
        float s = 0.0f;
        #pragma unroll
        for (int c = 0; c < 8; c++) s += kvp[c * 4096 + x];
        kv[x >> 6][x & 63] = s;
    }
    __syncthreads();
    const float* W = WoutAll + ((long)(z * 2 + layer)) * Dc * Dc + (long)h * 64 * Dc;
    int d = t >> 2, cq = t & 3;
    for (int ct = 0; ct < 6; ct++) {
        int c0 = ct * 128 + cq * 32;
        float acc[32];
        #pragma unroll
        for (int j = 0; j < 32; j++) acc[j] = 0.0f;
        for (int e = 0; e < 64; e++) {
            float kd = kv[d][e];
            const float* wr = W + (long)e * Dc + c0;
            #pragma unroll
            for (int j = 0; j < 32; j++) acc[j] = fmaf(kd, wr[j], acc[j]);
        }
        unsigned* gp = G + ((long)zb * Dc + h * 64 + d) * Dc + c0;
        #pragma unroll
        for (int j = 0; j < 32; j++) gp[j] = f2tf32(acc[j]);
    }
}

// --------------------------------- host ------------------------------------
static inline int cdiv(int a, int b) { return (a + b - 1) / b; }

extern "C" void kernel_launch(void* const* d_in, const int* in_sizes, int n_in,
                              void* d_out, int out_size) {
    (void)in_sizes; (void)n_in; (void)out_size;
    const float* in_x  = (const float*)d_in[0];
    const float* in_h  = (const float*)d_in[1];
    const float* in_sp = (const float*)d_in[2];
    const float* in_tp = (const float*)d_in[3];

    cudaFuncSetAttribute(tgemm<0>, cudaFuncAttributeMaxDynamicSharedMemorySize, TG_SMEM);
    cudaFuncSetAttribute(tgemm<1>, cudaFuncAttributeMaxDynamicSharedMemorySize, TG_SMEM);
    cudaFuncSetAttribute(tgemm<2>, cudaFuncAttributeMaxDynamicSharedMemorySize, TG_SMEM);
    cudaFuncSetAttribute(tgemm<3>, cudaFuncAttributeMaxDynamicSharedMemorySize, TG_SMEM);
    cudaFuncSetAttribute(tgemm<4>, cudaFuncAttributeMaxDynamicSharedMemorySize, TG_SMEM);

    float *pos, *xa, *xb, *h, *qkvpre, *qkv, *kvp, *x2;
    unsigned *xnall, *hn, *ln2, *qbuf, *t1, *G;
    unsigned *wq, *wqh, *w1, *w2;
    cudaGetSymbolAddress((void**)&pos,    g_pos);
    cudaGetSymbolAddress((void**)&xa,     g_xa);
    cudaGetSymbolAddress((void**)&xb,     g_xb);
    cudaGetSymbolAddress((void**)&h,      g_h);
    cudaGetSymbolAddress((void**)&qkvpre, g_qkvpre);
    cudaGetSymbolAddress((void**)&qkv,    g_qkv);
    cudaGetSymbolAddress((void**)&kvp,    g_kvp);
    cudaGetSymbolAddress((void**)&x2,     g_x2);
    cudaGetSymbolAddress((void**)&xnall,  g_xnall);
    cudaGetSymbolAddress((void**)&hn,     g_hn);
    cudaGetSymbolAddress((void**)&ln2,    g_ln2);
    cudaGetSymbolAddress((void**)&qbuf,   g_q);
    cudaGetSymbolAddress((void**)&t1,     g_t1);
    cudaGetSymbolAddress((void**)&G,      g_G);
    cudaGetSymbolAddress((void**)&wq,     g_Wqkv);
    cudaGetSymbolAddress((void**)&wqh,    g_Wqkvh);
    cudaGetSymbolAddress((void**)&w1,     g_W1);
    cudaGetSymbolAddress((void**)&w2,     g_W2);
    float* out = (float*)d_out;

    // prologue
    pos_kernel<<<cdiv(TOTc, 256), 256>>>(in_tp, in_sp, pos);
    vadd_kernel<<<cdiv(TOTc, 256), 256>>>(in_x, pos, xa, TOTc);
    wconv_kernel<<<cdiv(4 * Dc * D3c, 256), 256>>>((const float*)d_in[10], wq,  4l * Dc * D3c);
    wconv_kernel<<<cdiv(4 * Dc * D3c, 256), 256>>>((const float*)d_in[12], wqh, 4l * Dc * D3c);
    wconv_kernel<<<cdiv(4 * Dc * Mc,  256), 256>>>((const float*)d_in[16], w1,  4l * Dc * Mc);
    wconv_kernel<<<cdiv(4 * Mc * Dc,  256), 256>>>((const float*)d_in[18], w2,  4l * Mc * Dc);

    const long WQZ = 2l * Dc * D3c;   // dir stride (s4 = dir*2+layer)
    const long W1Z = 2l * Dc * Mc;
    const long W2Z = 2l * Mc * Dc;

    for (int layer = 0; layer < 2; layer++) {
        const float* lnig = (const float*)d_in[4] + (long)layer * Dc;
        const float* lnib = (const float*)d_in[5] + (long)layer * Dc;
        const float* lnhg = (const float*)d_in[6] + (long)layer * Dc;
        const float* lnhb = (const float*)d_in[7] + (long)layer * Dc;
        const float* lnog = (const float*)d_in[8] + (long)layer * Dc;
        const float* lnob = (const float*)d_in[9] + (long)layer * Dc;
        const float* bqkv  = (const float*)d_in[11] + (long)layer * D3c;
        const float* bqkvh = (const float*)d_in[13] + (long)layer * D3c;
        const float* bout  = (const float*)d_in[15] + (long)layer * Dc;
        const float* b1    = (const float*)d_in[17] + (long)layer * Mc;
        const float* b2    = (const float*)d_in[19] + (long)layer * Dc;
        const unsigned* Wq  = wq  + (long)layer * Dc * D3c;
        const unsigned* Wqh = wqh + (long)layer * Dc * D3c;
        const unsigned* W1p = w1  + (long)layer * Dc * Mc;
        const unsigned* W2p = w2  + (long)layer * Mc * Dc;

        const float* Xc = (layer == 0) ? xa : xb;
        float* Yc = (layer == 0) ? xb : out;
        // init Y: layer0 accumulates on top of pos (so Y == next X directly);
        // layer1 accumulates on top of zero (harness poisons d_out).
        if (layer == 0)
            copy_kernel<<<cdiv(TOTc, 256), 256>>>(pos, Yc, TOTc);
        else
            zero_kernel<<<cdiv(TOTc, 256), 256>>>(Yc, TOTc);

        // batched loop-invariant half, both dirs: pre = LN(x_t)@Wqkv + bqkv
        ln_xall_m<<<2 * BLNc, 256>>>(Xc, lnig, lnib, xnall);
        {
            EpiAux a = {};
            tgemm<0><<<dim3(D3c / 128, 2 * BLNc / 128), 128, TG_SMEM>>>(
                xnall, Dc, Wq, WQZ, D3c, bqkv, 2 * D3c,
                qkvpre, D3c, Dc, BLNc, BLNc, a);
        }
        hinit_kernel<<<cdiv(BNDc, 256), 256>>>(in_h, h);

        for (int ss = 0; ss < Lc; ss++) {
            int t0 = ss, t1s = Lc - 1 - ss;
            int tp0 = layer, tp1 = t1s;   // ref quirk: fwd uses pos[:, layer]

            ln_h_m<<<2 * BNc, 256>>>(h, pos, tp0, tp1, lnhg, lnhb, hn);

            EpiAux a2 = {};
            a2.pre = qkvpre; a2.t0 = t0; a2.t1 = t1s; a2.qo = qbuf;
            tgemm<2><<<dim3(D3c / 128, 2 * BNc / 128), 128, TG_SMEM>>>(
                hn, Dc, Wqh, WQZ, D3c, bqkvh, 2 * D3c,
                qkv, D3c, Dc, BNc, BNc, a2);

            kv_partial_m<<<dim3(Bc * Hc * 8, 2), 256>>>(qkv, kvp);
            kvG_kernel<<<dim3(Hc, 4), 256>>>(kvp, (const float*)d_in[14], layer, G);

            EpiAux a3 = {};
            a3.t0 = t0; a3.t1 = t1s; a3.X = Xc; a3.h = h;
            a3.pos = pos; a3.tp0 = tp0; a3.tp1 = tp1; a3.x2w = x2;
            tgemm<3><<<dim3(Dc / 128, 2 * BNc / 128), 128, TG_SMEM>>>(
                qbuf, Dc, G, (long)Dc * Dc, Dc, bout, 2 * Dc,
                x2, Dc, Dc, BNc, 1024, a3);

            ln2_m<<<2 * BNc, 256>>>(x2, lnog, lnob, ln2);

            EpiAux a1 = {};
            a1.t1o = t1;
            tgemm<1><<<dim3(Mc / 128, 2 * BNc / 128), 128, TG_SMEM>>>(
                ln2, Dc, W1p, W1Z, Mc, b1, 2 * Mc,
                nullptr, Mc, Dc, BNc, BNc, a1);

            EpiAux a4 = {};
            a4.t0 = t0; a4.t1 = t1s; a4.x2r = x2; a4.y = Yc;
            tgemm<4><<<dim3(Dc / 128, 2 * BNc / 128), 128, TG_SMEM>>>(
                t1, Mc, W2p, W2Z, Dc, b2, 2 * Dc,
                nullptr, Dc, Mc, BNc, BNc, a4);
        }
    }
}

// round 17
// speedup vs baseline: 1.6668x; 1.6668x over previous
#include <cuda_runtime.h>
#include <cuda_bf16.h>
#include <math.h>
#include <stdint.h>

// ---------------------------------------------------------------------------
// GPTrack2D encoder — tf32 mma.sync, pre-converted operands, BK=32 3-stage
// pipeline, merged fwd/bwd dirs (R15 baseline, 19.45 ms), plus R16':
// two-stream forked capture — the MLP branch (ln2/W1/W2/y-write) of step ss
// runs on stream s2 overlapped with step ss+1's recurrence chain on s1.
// x2/ln2/t1 are parity double-buffered; events close the distance-2 WAR.
// (R16's G-factorization reverted: kvG's scalar-load loop caused a 7.7 ms
// regression.)
// ---------------------------------------------------------------------------

#define Bc 2
#define Lc 12
#define Nc 1024
#define Dc 768
#define Hc 12
#define Mc 3072
#define D3c 2304
#define BNc (Bc*Nc)          /* 2048 */
#define BLNc (Bc*Lc*Nc)      /* 24576 */
#define NDc (Nc*Dc)
#define LNDc (Lc*Nc*Dc)
#define TOTc (Bc*Lc*Nc*Dc)
#define BNDc (Bc*Nc*Dc)

// ------------------------- device scratch (no allocs) ----------------------
__device__ float    g_pos   [TOTc];
__device__ float    g_x     [TOTc];
__device__ float    g_y2    [2l*TOTc];   // yf | yb contiguous
__device__ float    g_h     [2*BNDc];
__device__ float    g_qkvpre[2l*BLNc*D3c];
__device__ float    g_qkv   [2*BNc*D3c];
__device__ float    g_kvp   [2*Bc*Hc*8*64*64];
__device__ float    g_x2    [2][2*BNDc];       // parity double buffer
// tf32-bit-pattern (u32) activations
__device__ unsigned g_xnall [2*BLNc*Dc];
__device__ unsigned g_hn    [2*BNDc];
__device__ unsigned g_ln2   [2][2*BNDc];       // parity double buffer
__device__ unsigned g_o     [2*BNDc];
__device__ unsigned g_t1    [2][2l*BNc*Mc];    // parity double buffer
// tf32 weights ([s4][K][N], converted)
__device__ unsigned g_Wqkv  [4*Dc*D3c];
__device__ unsigned g_Wqkvh [4*Dc*D3c];
__device__ unsigned g_Wout  [4*Dc*Dc];
__device__ unsigned g_W1    [4*Dc*Mc];
__device__ unsigned g_W2    [4*Mc*Dc];

__device__ __forceinline__ float gelu_f(float x) {
    return 0.5f * x * (1.0f + erff(x * 0.70710678118654752440f));
}
__device__ __forceinline__ unsigned f2tf32(float x) {
    unsigned r;
    asm("cvt.rna.tf32.f32 %0, %1;" : "=r"(r) : "f"(x));
    return r;
}
__device__ __forceinline__ void mma_tf32(float c[4], unsigned a0, unsigned a1,
                                         unsigned a2, unsigned a3,
                                         unsigned b0, unsigned b1) {
    asm volatile(
        "mma.sync.aligned.m16n8k8.row.col.f32.tf32.tf32.f32 "
        "{%0,%1,%2,%3},{%4,%5,%6,%7},{%8,%9},{%0,%1,%2,%3};"
        : "+f"(c[0]), "+f"(c[1]), "+f"(c[2]), "+f"(c[3])
        : "r"(a0), "r"(a1), "r"(a2), "r"(a3), "r"(b0), "r"(b1));
}
__device__ __forceinline__ void cp16(unsigned* sdst, const void* gsrc) {
    unsigned s = (unsigned)__cvta_generic_to_shared(sdst);
    asm volatile("cp.async.cg.shared.global [%0], [%1], 16;" :: "r"(s), "l"(gsrc));
}

// ------------------------------- elementwise -------------------------------
__global__ void pos_kernel(const float* __restrict__ tpos,
                           const float* __restrict__ spos,
                           float* __restrict__ pos) {
    int idx = blockIdx.x * blockDim.x + threadIdx.x;
    if (idx >= TOTc) return;
    int d = idx % Dc;
    int n = (idx / Dc) % Nc;
    int l = (idx / NDc) % Lc;
    int b = idx / LNDc;
    pos[idx] = tpos[(b * Lc + l) * Dc + d] * spos[(b * Nc + n) * Dc + d];
}
__global__ void vadd_kernel(const float* __restrict__ a,
                            const float* __restrict__ b,
                            float* __restrict__ c, int n) {
    int idx = blockIdx.x * blockDim.x + threadIdx.x;
    if (idx < n) c[idx] = a[idx] + b[idx];
}
__global__ void combine_kernel(const float* __restrict__ yf,
                               const float* __restrict__ yb,
                               const float* __restrict__ pos,
                               float* __restrict__ dst, int n) {
    int idx = blockIdx.x * blockDim.x + threadIdx.x;
    if (idx < n) {
        float v = yf[idx] + yb[idx];
        if (pos) v += pos[idx];
        dst[idx] = v;
    }
}
__global__ void hinit_kernel(const float* __restrict__ src,
                             float* __restrict__ h) {
    int idx = blockIdx.x * blockDim.x + threadIdx.x;
    if (idx < BNDc) { h[idx] = src[idx]; h[idx + BNDc] = src[idx]; }
}
__global__ void wconv_kernel(const float* __restrict__ in,
                             unsigned* __restrict__ out, long n) {
    long idx = (long)blockIdx.x * blockDim.x + threadIdx.x;
    if (idx < n) out[idx] = f2tf32(in[idx]);
}

// ------------------------------- layernorm ---------------------------------
__device__ __forceinline__ void ln_row(float v0, float v1, float v2,
                                       const float* __restrict__ gam,
                                       const float* __restrict__ bet,
                                       unsigned* __restrict__ dp, int t,
                                       float* red) {
    float s = v0 + v1 + v2;
    #pragma unroll
    for (int o = 16; o > 0; o >>= 1) s += __shfl_down_sync(0xffffffffu, s, o);
    if ((t & 31) == 0) red[t >> 5] = s;
    __syncthreads();
    if (t < 32) {
        float x = (t < 8) ? red[t] : 0.0f;
        #pragma unroll
        for (int o = 4; o > 0; o >>= 1) x += __shfl_down_sync(0xffffffffu, x, o);
        if (t == 0) red[0] = x;
    }
    __syncthreads();
    float m = red[0] * (1.0f / 768.0f);
    __syncthreads();
    float d0 = v0 - m, d1 = v1 - m, d2 = v2 - m;
    float q2 = d0 * d0 + d1 * d1 + d2 * d2;
    #pragma unroll
    for (int o = 16; o > 0; o >>= 1) q2 += __shfl_down_sync(0xffffffffu, q2, o);
    if ((t & 31) == 0) red[t >> 5] = q2;
    __syncthreads();
    if (t < 32) {
        float x = (t < 8) ? red[t] : 0.0f;
        #pragma unroll
        for (int o = 4; o > 0; o >>= 1) x += __shfl_down_sync(0xffffffffu, x, o);
        if (t == 0) red[0] = x;
    }
    __syncthreads();
    float r = rsqrtf(red[0] * (1.0f / 768.0f) + 1e-5f);
    dp[t]       = f2tf32(d0 * r * gam[t]       + bet[t]);
    dp[t + 256] = f2tf32(d1 * r * gam[t + 256] + bet[t + 256]);
    dp[t + 512] = f2tf32(d2 * r * gam[t + 512] + bet[t + 512]);
}

__global__ void ln_xall_m(const float* __restrict__ X,
                          const float* __restrict__ gbase,
                          const float* __restrict__ bbase,
                          unsigned* __restrict__ dst) {
    __shared__ float red[32];
    int R = blockIdx.x;
    int z = R / BLNc;
    int R2 = R - z * BLNc;
    int tt = R2 / BNc;
    int rr = R2 - tt * BNc;
    int b = rr >> 10, n = rr & 1023;
    const float* p = X + (long)b * LNDc + (long)tt * NDc + (long)n * Dc;
    const float* gam = gbase + (long)z * 2 * Dc;
    const float* bet = bbase + (long)z * 2 * Dc;
    int t = threadIdx.x;
    ln_row(p[t], p[t + 256], p[t + 512], gam, bet, dst + (long)R * Dc, t, red);
}

__global__ void ln_h_m(const float* __restrict__ h,
                       const float* __restrict__ pos, int tp0, int tp1,
                       const float* __restrict__ gbase,
                       const float* __restrict__ bbase,
                       unsigned* __restrict__ dst) {
    __shared__ float red[32];
    int row = blockIdx.x;
    int z = row >> 11;
    int lrow = row & 2047;
    int b = lrow >> 10, n = lrow & 1023;
    const float* p = h + (long)row * Dc;
    int tp = z ? tp1 : tp0;
    const float* q = pos + (long)b * LNDc + (long)tp * NDc + (long)n * Dc;
    const float* gam = gbase + (long)z * 2 * Dc;
    const float* bet = bbase + (long)z * 2 * Dc;
    int t = threadIdx.x;
    ln_row(p[t] + q[t], p[t + 256] + q[t + 256], p[t + 512] + q[t + 512],
           gam, bet, dst + (long)row * Dc, t, red);
}

__global__ void ln2_m(const float* __restrict__ x2,
                      const float* __restrict__ gbase,
                      const float* __restrict__ bbase,
                      unsigned* __restrict__ dst) {
    __shared__ float red[32];
    int row = blockIdx.x;
    int z = row >> 11;
    const float* p = x2 + (long)row * Dc;
    const float* gam = gbase + (long)z * 2 * Dc;
    const float* bet = bbase + (long)z * 2 * Dc;
    int t = threadIdx.x;
    ln_row(p[t], p[t + 256], p[t + 512], gam, bet, dst + (long)row * Dc, t, red);
}

// ----------------------------- tf32 MMA GEMM -------------------------------
struct EpiAux {
    const float* pre; int t0, t1;  // EPI2 (+ EPI3/4 reuse t0/t1)
    const float* X;                // EPI3
    float* h;                      // EPI3 [2*BNDc]
    const float* pos; int tp0, tp1;// EPI3
    float* x2w;                    // EPI3
    const float* x2r;              // EPI4
    float* y;                      // EPI4 [2*TOTc] contiguous (yf | yb)
    unsigned* t1o;                 // EPI1
};

#define ASTR 36
#define BSTR 136
#define A_ST (128 * ASTR)
#define B_ST (32 * BSTR)
#define TG_SMEM (3 * (A_ST + B_ST) * 4)   /* 107,520 B */

template<int EPI>
__global__ void __launch_bounds__(128)
tgemm(const unsigned* __restrict__ A, int lda,
      const unsigned* __restrict__ B, long bzstr, int ldb,
      const float* __restrict__ bias, long bizstr,
      float* __restrict__ C, int N, int K, int Mper, EpiAux aux) {
    extern __shared__ unsigned smem[];
    unsigned* Asm = smem;
    unsigned* Bsm = smem + 3 * A_ST;

    const int tid = threadIdx.x;
    const int lane = tid & 31;
    const int wid = tid >> 5;
    const int warp_m = (wid >> 1) * 64;
    const int warp_n = (wid & 1) * 64;
    const int bx = blockIdx.x, by = blockIdx.y;
    const int r = lane >> 2, cq = lane & 3;
    const int row0 = by * 128;
    const int dir = (row0 >= Mper) ? 1 : 0;
    const unsigned* Bd = B + (long)dir * bzstr;
    const float* biasd = bias + (long)dir * bizstr;

    float acc[4][8][4];
    #pragma unroll
    for (int i = 0; i < 4; i++)
        #pragma unroll
        for (int j = 0; j < 8; j++)
            #pragma unroll
            for (int q = 0; q < 4; q++) acc[i][j][q] = 0.0f;

    const int S = K / 32;

    auto issue_stage = [&](int s) {
        int st = s % 3;
        int k0 = s * 32;
        unsigned* Ad = Asm + st * A_ST;
        unsigned* Bs = Bsm + st * B_ST;
        #pragma unroll
        for (int i = 0; i < 8; i++) {
            int lid = tid + i * 128;
            int am = lid >> 3, ak = (lid & 7) * 4;
            cp16(Ad + am * ASTR + ak, A + (long)(row0 + am) * lda + k0 + ak);
        }
        #pragma unroll
        for (int i = 0; i < 8; i++) {
            int lid = tid + i * 128;
            int br = lid >> 5, bc = (lid & 31) * 4;
            cp16(Bs + br * BSTR + bc, Bd + (long)(k0 + br) * ldb + bx * 128 + bc);
        }
    };

    issue_stage(0);
    asm volatile("cp.async.commit_group;");
    issue_stage(1);
    asm volatile("cp.async.commit_group;");

    for (int s = 0; s < S; s++) {
        if (s + 2 < S) {
            issue_stage(s + 2);
            asm volatile("cp.async.commit_group;");
            asm volatile("cp.async.wait_group 2;");
        } else if (s + 1 < S) {
            asm volatile("cp.async.wait_group 1;");
        } else {
            asm volatile("cp.async.wait_group 0;");
        }
        __syncthreads();
        const int st = s % 3;
        const unsigned* Ad = Asm + st * A_ST;
        const unsigned* Bs = Bsm + st * B_ST;
        #pragma unroll
        for (int ka = 0; ka < 4; ka++) {
            const int kb = ka * 8;
            unsigned af[4][4], bf[8][2];
            #pragma unroll
            for (int mi = 0; mi < 4; mi++) {
                int m0 = warp_m + mi * 16 + r;
                af[mi][0] = Ad[m0 * ASTR + kb + cq];
                af[mi][1] = Ad[(m0 + 8) * ASTR + kb + cq];
                af[mi][2] = Ad[m0 * ASTR + kb + cq + 4];
                af[mi][3] = Ad[(m0 + 8) * ASTR + kb + cq + 4];
            }
            #pragma unroll
            for (int ni = 0; ni < 8; ni++) {
                int n0 = warp_n + ni * 8 + r;
                bf[ni][0] = Bs[(kb + cq) * BSTR + n0];
                bf[ni][1] = Bs[(kb + cq + 4) * BSTR + n0];
            }
            #pragma unroll
            for (int mi = 0; mi < 4; mi++)
                #pragma unroll
                for (int ni = 0; ni < 8; ni++)
                    mma_tf32(acc[mi][ni], af[mi][0], af[mi][1], af[mi][2],
                             af[mi][3], bf[ni][0], bf[ni][1]);
        }
        __syncthreads();
    }

    // ---- epilogue ----
    const int t_z  = dir ? aux.t1 : aux.t0;
    const int tp_z = dir ? aux.tp1 : aux.tp0;
    #pragma unroll
    for (int mi = 0; mi < 4; mi++) {
        #pragma unroll
        for (int ni = 0; ni < 8; ni++) {
            int col = bx * 128 + warp_n + ni * 8 + 2 * cq;
            float bs0 = biasd[col], bs1 = biasd[col + 1];
            #pragma unroll
            for (int half = 0; half < 2; half++) {
                int row = row0 + warp_m + mi * 16 + r + half * 8;
                float v0 = acc[mi][ni][half * 2 + 0] + bs0;
                float v1 = acc[mi][ni][half * 2 + 1] + bs1;
                if (EPI == 0) {
                    float* cp = C + (long)row * N + col;
                    cp[0] = v0; cp[1] = v1;
                } else if (EPI == 1) {
                    unsigned* tp = aux.t1o + (long)row * N + col;
                    tp[0] = f2tf32(gelu_f(v0));
                    tp[1] = f2tf32(gelu_f(v1));
                } else if (EPI == 2) {
                    int lrow = row - dir * 2048;
                    const float* pp = aux.pre
                        + ((long)dir * Lc + t_z) * BNc * D3c
                        + (long)lrow * D3c + col;
                    v0 += pp[0]; v1 += pp[1];
                    if (col < 1536)     v0 = (v0 > 0.f) ? v0 + 1.f : expf(v0);
                    if (col + 1 < 1536) v1 = (v1 > 0.f) ? v1 + 1.f : expf(v1);
                    float* cp = C + (long)row * N + col;
                    cp[0] = v0; cp[1] = v1;
                } else if (EPI == 3) {
                    int lrow = row & 2047;
                    int b = lrow >> 10, rr = lrow & 1023;
                    long xb = (long)b * LNDc + (long)t_z * NDc + (long)rr * Dc + col;
                    long pb = (long)b * LNDc + (long)tp_z * NDc + (long)rr * Dc + col;
                    long idx = (long)row * Dc + col;
                    aux.x2w[idx]     = v0 + aux.X[xb];
                    aux.x2w[idx + 1] = v1 + aux.X[xb + 1];
                    aux.h[idx]     = v0 + aux.h[idx]     + aux.pos[pb];
                    aux.h[idx + 1] = v1 + aux.h[idx + 1] + aux.pos[pb + 1];
                } else if (EPI == 4) {
                    int lrow = row & 2047;
                    int b = lrow >> 10, rr = lrow & 1023;
                    long idx = (long)row * Dc + col;
                    float w0 = v0 + aux.x2r[idx];
                    float w1 = v1 + aux.x2r[idx + 1];
                    long yo = (long)dir * TOTc + (long)b * LNDc
                            + (long)t_z * NDc + (long)rr * Dc + col;
                    aux.y[yo] = w0; aux.y[yo + 1] = w1;
                }
            }
        }
    }
}

// ----------------------- linear-attention small GEMMs ----------------------
__global__ void kv_partial_m(const float* __restrict__ qkvg,
                             float* __restrict__ kvpg) {
    int z = blockIdx.y;
    const float* qkv = qkvg + (long)z * BNc * D3c;
    float* kvp = kvpg + (long)z * Bc * Hc * 8 * 4096;
    int chunk = blockIdx.x & 7;
    int bh = blockIdx.x >> 3;
    int h = bh % Hc, b = bh / Hc;
    int t = threadIdx.x;
    __shared__ float ks[8][64], vs[8][64];
    int d0 = (t & 15) * 4, e0 = (t >> 4) * 4;
    float acc[4][4];
    #pragma unroll
    for (int i = 0; i < 4; i++)
        #pragma unroll
        for (int j = 0; j < 4; j++) acc[i][j] = 0.0f;
    int j0 = chunk * 128;
    const float* kbase = qkv + (long)(b * Nc) * D3c + Dc + h * 64;
    const float* vbase = kbase + Dc;
    for (int js = 0; js < 128; js += 8) {
        #pragma unroll
        for (int rr = 0; rr < 2; rr++) {
            int id = t + rr * 256;
            int jj = id >> 6, dd = id & 63;
            long roff = (long)(j0 + js + jj) * D3c + dd;
            ks[jj][dd] = kbase[roff];
            vs[jj][dd] = vbase[roff];
        }
        __syncthreads();
        #pragma unroll
        for (int jj = 0; jj < 8; jj++) {
            float kd[4], ve[4];
            *(float4*)kd = *(const float4*)&ks[jj][d0];
            *(float4*)ve = *(const float4*)&vs[jj][e0];
            #pragma unroll
            for (int i = 0; i < 4; i++)
                #pragma unroll
                for (int j = 0; j < 4; j++)
                    acc[i][j] = fmaf(kd[i], ve[j], acc[i][j]);
        }
        __syncthreads();
    }
    float* dst = kvp + ((long)bh * 8 + chunk) * 4096;
    #pragma unroll
    for (int i = 0; i < 4; i++)
        #pragma unroll
        for (int j = 0; j < 4; j++)
            dst[(d0 + i) * 64 + e0 + j] = acc[i][j];
}

__global__ void o_kernel_m(const float* __restrict__ qkvg,
                           const float* __restrict__ kvpg,
                           unsigned* __restrict__ og) {
    int z = blockIdx.y;
    const float* qkv = qkvg + (long)z * BNc * D3c;
    const float* kvp = kvpg + (long)z * Bc * Hc * 8 * 4096;
    unsigned* o = og + (long)z * BNDc;
    int ic = blockIdx.x & 7;
    int bh = blockIdx.x >> 3;
    int h = bh % Hc, b = bh / Hc;
    int t = threadIdx.x;
    __shared__ float kvs[4096];
    const float* src = kvp + (long)bh * 8 * 4096;
    for (int x = t; x < 4096; x += 256) {
        float s = 0.0f;
        #pragma unroll
        for (int c = 0; c < 8; c++) s += src[c * 4096 + x];
        kvs[x] = s;
    }
    __syncthreads();
    int i = ic * 128 + (t >> 1);
    int e0 = (t & 1) * 32;
    const float* qrow = qkv + (long)(b * Nc + i) * D3c + h * 64;
    float acc[32];
    #pragma unroll
    for (int g = 0; g < 32; g++) acc[g] = 0.0f;
    #pragma unroll 4
    for (int d = 0; d < 64; d++) {
        float qv = qrow[d];
        #pragma unroll
        for (int g = 0; g < 8; g++) {
            float4 kvv = *(const float4*)&kvs[d * 64 + e0 + g * 4];
            acc[g * 4 + 0] = fmaf(qv, kvv.x, acc[g * 4 + 0]);
            acc[g * 4 + 1] = fmaf(qv, kvv.y, acc[g * 4 + 1]);
            acc[g * 4 + 2] = fmaf(qv, kvv.z, acc[g * 4 + 2]);
            acc[g * 4 + 3] = fmaf(qv, kvv.w, acc[g * 4 + 3]);
        }
    }
    long ob = (long)(b * Nc + i) * Dc + h * 64 + e0;
    #pragma unroll
    for (int g = 0; g < 32; g++) o[ob + g] = f2tf32(acc[g]);
}

// --------------------------------- host ------------------------------------
static inline int cdiv(int a, int b) { return (a + b - 1) / b; }

extern "C" void kernel_launch(void* const* d_in, const int* in_sizes, int n_in,
                              void* d_out, int out_size) {
    (void)in_sizes; (void)n_in; (void)out_size;
    const float* in_x  = (const float*)d_in[0];
    const float* in_h  = (const float*)d_in[1];
    const float* in_sp = (const float*)d_in[2];
    const float* in_tp = (const float*)d_in[3];

    // one-time stream/event setup (first call is the uncaptured correctness
    // run; capture call reuses them — record/wait become graph edges)
    static cudaStream_t s1 = nullptr, s2 = nullptr;
    static cudaEvent_t evA[2][Lc], evM[2][Lc], evb, eve;
    if (!s1) {
        cudaStreamCreateWithFlags(&s1, cudaStreamNonBlocking);
        cudaStreamCreateWithFlags(&s2, cudaStreamNonBlocking);
        for (int l = 0; l < 2; l++)
            for (int s = 0; s < Lc; s++) {
                cudaEventCreateWithFlags(&evA[l][s], cudaEventDisableTiming);
                cudaEventCreateWithFlags(&evM[l][s], cudaEventDisableTiming);
            }
        cudaEventCreateWithFlags(&evb, cudaEventDisableTiming);
        cudaEventCreateWithFlags(&eve, cudaEventDisableTiming);
    }

    cudaFuncSetAttribute(tgemm<0>, cudaFuncAttributeMaxDynamicSharedMemorySize, TG_SMEM);
    cudaFuncSetAttribute(tgemm<1>, cudaFuncAttributeMaxDynamicSharedMemorySize, TG_SMEM);
    cudaFuncSetAttribute(tgemm<2>, cudaFuncAttributeMaxDynamicSharedMemorySize, TG_SMEM);
    cudaFuncSetAttribute(tgemm<3>, cudaFuncAttributeMaxDynamicSharedMemorySize, TG_SMEM);
    cudaFuncSetAttribute(tgemm<4>, cudaFuncAttributeMaxDynamicSharedMemorySize, TG_SMEM);

    float *pos, *X, *y2, *h, *qkvpre, *qkv, *kvp;
    float *x2b;       // base of parity pair
    unsigned *xnall, *hn, *ln2b, *o, *t1b;
    unsigned *wq, *wqh, *wo, *w1, *w2;
    cudaGetSymbolAddress((void**)&pos,    g_pos);
    cudaGetSymbolAddress((void**)&X,      g_x);
    cudaGetSymbolAddress((void**)&y2,     g_y2);
    cudaGetSymbolAddress((void**)&h,      g_h);
    cudaGetSymbolAddress((void**)&qkvpre, g_qkvpre);
    cudaGetSymbolAddress((void**)&qkv,    g_qkv);
    cudaGetSymbolAddress((void**)&kvp,    g_kvp);
    cudaGetSymbolAddress((void**)&x2b,    g_x2);
    cudaGetSymbolAddress((void**)&xnall,  g_xnall);
    cudaGetSymbolAddress((void**)&hn,     g_hn);
    cudaGetSymbolAddress((void**)&ln2b,   g_ln2);
    cudaGetSymbolAddress((void**)&o,      g_o);
    cudaGetSymbolAddress((void**)&t1b,    g_t1);
    cudaGetSymbolAddress((void**)&wq,     g_Wqkv);
    cudaGetSymbolAddress((void**)&wqh,    g_Wqkvh);
    cudaGetSymbolAddress((void**)&wo,     g_Wout);
    cudaGetSymbolAddress((void**)&w1,     g_W1);
    cudaGetSymbolAddress((void**)&w2,     g_W2);
    float* out = (float*)d_out;
    float* yf = y2;
    float* yb = y2 + (long)TOTc;

    // bridge default(capture) stream -> s1, s2
    cudaEventRecord(evb, 0);
    cudaStreamWaitEvent(s1, evb, 0);
    cudaStreamWaitEvent(s2, evb, 0);

    // prologue (s1)
    pos_kernel<<<cdiv(TOTc, 256), 256, 0, s1>>>(in_tp, in_sp, pos);
    vadd_kernel<<<cdiv(TOTc, 256), 256, 0, s1>>>(in_x, pos, X, TOTc);
    wconv_kernel<<<cdiv(4 * Dc * D3c, 256), 256, 0, s1>>>((const float*)d_in[10], wq,  4l * Dc * D3c);
    wconv_kernel<<<cdiv(4 * Dc * D3c, 256), 256, 0, s1>>>((const float*)d_in[12], wqh, 4l * Dc * D3c);
    wconv_kernel<<<cdiv(4 * Dc * Dc,  256), 256, 0, s1>>>((const float*)d_in[14], wo,  4l * Dc * Dc);
    wconv_kernel<<<cdiv(4 * Dc * Mc,  256), 256, 0, s1>>>((const float*)d_in[16], w1,  4l * Dc * Mc);
    wconv_kernel<<<cdiv(4 * Mc * Dc,  256), 256, 0, s1>>>((const float*)d_in[18], w2,  4l * Mc * Dc);

    const long WQZ = 2l * Dc * D3c;
    const long WOZ = 2l * Dc * Dc;
    const long W1Z = 2l * Dc * Mc;
    const long W2Z = 2l * Mc * Dc;

    for (int layer = 0; layer < 2; layer++) {
        const float* lnig = (const float*)d_in[4] + (long)layer * Dc;
        const float* lnib = (const float*)d_in[5] + (long)layer * Dc;
        const float* lnhg = (const float*)d_in[6] + (long)layer * Dc;
        const float* lnhb = (const float*)d_in[7] + (long)layer * Dc;
        const float* lnog = (const float*)d_in[8] + (long)layer * Dc;
        const float* lnob = (const float*)d_in[9] + (long)layer * Dc;
        const float* bqkv  = (const float*)d_in[11] + (long)layer * D3c;
        const float* bqkvh = (const float*)d_in[13] + (long)layer * D3c;
        const float* bout  = (const float*)d_in[15] + (long)layer * Dc;
        const float* b1    = (const float*)d_in[17] + (long)layer * Mc;
        const float* b2    = (const float*)d_in[19] + (long)layer * Dc;
        const unsigned* Wq  = wq  + (long)layer * Dc * D3c;
        const unsigned* Wqh = wqh + (long)layer * Dc * D3c;
        const unsigned* Wo  = wo  + (long)layer * Dc * Dc;
        const unsigned* W1p = w1  + (long)layer * Dc * Mc;
        const unsigned* W2p = w2  + (long)layer * Mc * Dc;

        ln_xall_m<<<2 * BLNc, 256, 0, s1>>>(X, lnig, lnib, xnall);
        {
            EpiAux a = {};
            tgemm<0><<<dim3(D3c / 128, 2 * BLNc / 128), 128, TG_SMEM, s1>>>(
                xnall, Dc, Wq, WQZ, D3c, bqkv, 2 * D3c,
                qkvpre, D3c, Dc, BLNc, a);
        }
        hinit_kernel<<<cdiv(BNDc, 256), 256, 0, s1>>>(in_h, h);

        for (int ss = 0; ss < Lc; ss++) {
            int t0 = ss, t1s = Lc - 1 - ss;
            int tp0 = layer, tp1 = t1s;   // ref quirk: fwd uses pos[:, layer]
            int p = ss & 1;
            float*    x2p  = x2b  + (long)p * 2 * BNDc;
            unsigned* ln2p = ln2b + (long)p * 2 * BNDc;
            unsigned* t1p  = t1b  + (long)p * 2l * BNc * Mc;

            // ---- recurrence chain (s1) ----
            ln_h_m<<<2 * BNc, 256, 0, s1>>>(h, pos, tp0, tp1, lnhg, lnhb, hn);

            EpiAux a2 = {};
            a2.pre = qkvpre; a2.t0 = t0; a2.t1 = t1s;
            tgemm<2><<<dim3(D3c / 128, 2 * BNc / 128), 128, TG_SMEM, s1>>>(
                hn, Dc, Wqh, WQZ, D3c, bqkvh, 2 * D3c,
                qkv, D3c, Dc, BNc, a2);

            kv_partial_m<<<dim3(Bc * Hc * 8, 2), 256, 0, s1>>>(qkv, kvp);
            o_kernel_m<<<dim3(Bc * Hc * 8, 2), 256, 0, s1>>>(qkv, kvp, o);

            // WAR: tgemm<3> rewrites x2[p]; MLP(ss-2) (same parity) must be done
            if (ss >= 2) cudaStreamWaitEvent(s1, evM[layer][ss - 2], 0);

            EpiAux a3 = {};
            a3.t0 = t0; a3.t1 = t1s; a3.X = X; a3.h = h;
            a3.pos = pos; a3.tp0 = tp0; a3.tp1 = tp1; a3.x2w = x2p;
            tgemm<3><<<dim3(Dc / 128, 2 * BNc / 128), 128, TG_SMEM, s1>>>(
                o, Dc, Wo, WOZ, Dc, bout, 2 * Dc,
                x2p, Dc, Dc, BNc, a3);

            cudaEventRecord(evA[layer][ss], s1);

            // ---- MLP branch (s2), overlapped with next step's chain ----
            cudaStreamWaitEvent(s2, evA[layer][ss], 0);

            ln2_m<<<2 * BNc, 256, 0, s2>>>(x2p, lnog, lnob, ln2p);

            EpiAux a1 = {};
            a1.t1o = t1p;
            tgemm<1><<<dim3(Mc / 128, 2 * BNc / 128), 128, TG_SMEM, s2>>>(
                ln2p, Dc, W1p, W1Z, Mc, b1, 2 * Mc,
                nullptr, Mc, Dc, BNc, a1);

            EpiAux a4 = {};
            a4.t0 = t0; a4.t1 = t1s; a4.x2r = x2p; a4.y = y2;
            tgemm<4><<<dim3(Dc / 128, 2 * BNc / 128), 128, TG_SMEM, s2>>>(
                t1p, Mc, W2p, W2Z, Dc, b2, 2 * Dc,
                nullptr, Dc, Mc, BNc, a4);

            cudaEventRecord(evM[layer][ss], s2);
        }

        // join: combine needs all of this layer's MLP writes to y2
        cudaStreamWaitEvent(s1, evM[layer][Lc - 1], 0);
        if (layer == 0)
            combine_kernel<<<cdiv(TOTc, 256), 256, 0, s1>>>(yf, yb, pos, X, TOTc);
        else
            combine_kernel<<<cdiv(TOTc, 256), 256, 0, s1>>>(yf, yb, nullptr, out, TOTc);
    }

    // bridge back to default(capture) stream
    cudaEventRecord(eve, s1);
    cudaStreamWaitEvent(0, eve, 0);
}